// round 2
// baseline (speedup 1.0000x reference)
#include <cuda_runtime.h>

#define BATCH 4096
#define TLEN 2048
#define BDIM 256
#define NWARP 8
#define NCAT 150          // 100 mcc + 50 tr, combined index space
#define CPAD 152          // padded replica stride
#define NCOLS 456
#define EPS 1e-9f

__global__ __launch_bounds__(BDIM) void agg_feature_kernel(
    const float* __restrict__ amount,
    const int*   __restrict__ mcc,
    const int*   __restrict__ tr,
    const int*   __restrict__ seq_lens,
    float*       __restrict__ out)
{
    __shared__ float s_cnt[NWARP * CPAD];
    __shared__ float s_sum[NWARP * CPAD];
    __shared__ float s_ssq[NWARP * CPAD];
    __shared__ float s_tot[NWARP];
    __shared__ float s_tot2[NWARP];
    __shared__ int   s_distinct[2];

    const int b    = blockIdx.x;
    const int tid  = threadIdx.x;
    const int wid  = tid >> 5;
    const int lane = tid & 31;

    // hoist scalar load so it overlaps the mainloop
    float sl = 0.f;
    if (tid == 0) sl = (float)seq_lens[b];

    // zero histograms
    #pragma unroll
    for (int i = tid; i < NWARP * CPAD; i += BDIM) {
        s_cnt[i] = 0.f; s_sum[i] = 0.f; s_ssq[i] = 0.f;
    }
    if (tid < 2) s_distinct[tid] = 0;
    __syncthreads();

    float* cnt = s_cnt + wid * CPAD;   // per-warp replica
    float* sum = s_sum + wid * CPAD;
    float* ssq = s_ssq + wid * CPAD;

    const float4* a4 = (const float4*)(amount + (size_t)b * TLEN);
    const int4*   m4 = (const int4*)  (mcc    + (size_t)b * TLEN);
    const int4*   t4 = (const int4*)  (tr     + (size_t)b * TLEN);

    float tot = 0.f, tot2 = 0.f;

    // T/4 = 512 vec4 elements, 256 threads -> 2 iterations
    #pragma unroll
    for (int it = 0; it < TLEN / 4 / BDIM; it++) {
        const int idx = it * BDIM + tid;
        float4 a = a4[idx];
        int4   m = m4[idx];
        int4   t = t4[idx];

        float v;
        v = a.x; tot += v; tot2 += v * v;
        atomicAdd(&cnt[m.x], 1.f); atomicAdd(&sum[m.x], v); atomicAdd(&ssq[m.x], v * v);
        atomicAdd(&cnt[100 + t.x], 1.f); atomicAdd(&sum[100 + t.x], v); atomicAdd(&ssq[100 + t.x], v * v);

        v = a.y; tot += v; tot2 += v * v;
        atomicAdd(&cnt[m.y], 1.f); atomicAdd(&sum[m.y], v); atomicAdd(&ssq[m.y], v * v);
        atomicAdd(&cnt[100 + t.y], 1.f); atomicAdd(&sum[100 + t.y], v); atomicAdd(&ssq[100 + t.y], v * v);

        v = a.z; tot += v; tot2 += v * v;
        atomicAdd(&cnt[m.z], 1.f); atomicAdd(&sum[m.z], v); atomicAdd(&ssq[m.z], v * v);
        atomicAdd(&cnt[100 + t.z], 1.f); atomicAdd(&sum[100 + t.z], v); atomicAdd(&ssq[100 + t.z], v * v);

        v = a.w; tot += v; tot2 += v * v;
        atomicAdd(&cnt[m.w], 1.f); atomicAdd(&sum[m.w], v); atomicAdd(&ssq[m.w], v * v);
        atomicAdd(&cnt[100 + t.w], 1.f); atomicAdd(&sum[100 + t.w], v); atomicAdd(&ssq[100 + t.w], v * v);
    }

    // block reduce row totals
    #pragma unroll
    for (int off = 16; off > 0; off >>= 1) {
        tot  += __shfl_down_sync(0xFFFFFFFFu, tot,  off);
        tot2 += __shfl_down_sync(0xFFFFFFFFu, tot2, off);
    }
    if (lane == 0) { s_tot[wid] = tot; s_tot2[wid] = tot2; }
    __syncthreads();

    float* rowout = out + (size_t)b * NCOLS;

    if (tid == 0) {
        float S = 0.f, Q = 0.f;
        #pragma unroll
        for (int r = 0; r < NWARP; r++) { S += s_tot[r]; Q += s_tot2[r]; }
        rowout[0] = sl;
        rowout[1] = S;
        rowout[2] = S / (sl + EPS);
        float a = fmaxf(Q - S * S / (sl + EPS), 0.f);
        rowout[3] = sqrtf(a / (fmaxf(sl - 1.f, 0.f) + EPS));
    }

    // per-category fold + stats
    if (tid < NCAT) {
        float c = 0.f, s = 0.f, q = 0.f;
        #pragma unroll
        for (int r = 0; r < NWARP; r++) {
            c += s_cnt[r * CPAD + tid];
            s += s_sum[r * CPAD + tid];
            q += s_ssq[r * CPAD + tid];
        }
        const bool  ismcc = tid < 100;
        const int   local = ismcc ? tid : tid - 100;
        const float mask  = (local > 0) ? 1.f : 0.f;
        const float ec    = c * mask;
        const float mean  = s / (ec + EPS);
        float a = fmaxf(q - s * s / (ec + EPS), 0.f);
        const float stdv  = sqrtf(a / (fmaxf(ec - 1.f, 0.f) + EPS));

        const int base = ismcc ? 4 : 304;
        const int C    = ismcc ? 100 : 50;
        rowout[base + local]         = ec;
        rowout[base + C + local]     = mean;
        rowout[base + 2 * C + local] = stdv;

        if (ec > 0.f) atomicAdd(&s_distinct[ismcc ? 0 : 1], 1);
    }
    __syncthreads();
    if (tid < 2) rowout[454 + tid] = (float)s_distinct[tid];
}

extern "C" void kernel_launch(void* const* d_in, const int* in_sizes, int n_in,
                              void* d_out, int out_size)
{
    const float* amount   = (const float*)d_in[0];
    const int*   mcc      = (const int*)  d_in[1];
    const int*   tr_type  = (const int*)  d_in[2];
    const int*   seq_lens = (const int*)  d_in[3];
    float*       out      = (float*)d_out;

    agg_feature_kernel<<<BATCH, BDIM>>>(amount, mcc, tr_type, seq_lens, out);
}